// round 9
// baseline (speedup 1.0000x reference)
#include <cuda_runtime.h>
#include <cstdint>

#define NN 50000
#define EE 800000

// ---------------- scratch (device globals, referenced directly) -------------
__device__ float g_y[NN * 128];      // x @ Wl  (per layer)
__device__ float g_z[NN * 128];      // x @ Wr + b
__device__ float g_h[NN * 128];      // layer activation
__device__ int   g_rowptr[NN + 1];   // CSR row pointers (by dst)
__device__ int   g_cnt[NN];          // in-degree histogram
__device__ int   g_cursor[NN];       // fill cursors
__device__ int   g_eidx[EE];         // src node id per CSR slot
__device__ int   g_is64;             // edge_index dtype flag

// ---------------- edge_index dtype detection --------------------------------
// If the buffer is really int64, every value is in [0, NN). If it is int32
// data misread as int64, the hi word is a node id (nonzero w.p. 1-1/50000),
// making the value >= 2^32. 64 samples -> misclassification impossible in
// practice.
__global__ void detect_dtype(const void* __restrict__ ei) {
    if (threadIdx.x != 0 || blockIdx.x != 0) return;
    const long long* p = (const long long*)ei;
    int ok64 = 1;
    for (int i = 0; i < 64; i++) {
        long long v = p[i];
        if (v < 0 || v >= NN) { ok64 = 0; break; }
    }
    g_is64 = ok64;
}

// which: 0 = src row, 1 = dst row
__device__ __forceinline__ int load_idx(const void* __restrict__ ei, int which, int e) {
    if (g_is64) {
        const long long* p = (const long long*)ei;
        return (int)p[(size_t)which * EE + e];
    } else {
        const int* p = (const int*)ei;
        return p[(size_t)which * EE + e];
    }
}

// ---------------- CSR build ----------------
__global__ void csr_clear() {
    int i = blockIdx.x * blockDim.x + threadIdx.x;
    if (i < NN) { g_cnt[i] = 0; g_cursor[i] = 0; }
}

__global__ void csr_hist(const void* __restrict__ ei) {
    int e = blockIdx.x * blockDim.x + threadIdx.x;
    if (e < EE) atomicAdd(&g_cnt[load_idx(ei, 1, e)], 1);
}

// single-block chunked exclusive scan over g_cnt -> g_rowptr
__global__ void __launch_bounds__(1024) csr_scan() {
    __shared__ int sh[1024];
    __shared__ int carry;
    if (threadIdx.x == 0) carry = 0;
    __syncthreads();
    for (int base = 0; base < NN; base += 1024) {
        int i = base + threadIdx.x;
        int v = (i < NN) ? g_cnt[i] : 0;
        sh[threadIdx.x] = v;
        __syncthreads();
#pragma unroll
        for (int off = 1; off < 1024; off <<= 1) {
            int t = (threadIdx.x >= off) ? sh[threadIdx.x - off] : 0;
            __syncthreads();
            sh[threadIdx.x] += t;
            __syncthreads();
        }
        int incl = sh[threadIdx.x];
        if (i < NN) g_rowptr[i] = carry + (incl - v);
        __syncthreads();                       // all reads of carry done
        if (threadIdx.x == 1023) carry += incl;
        __syncthreads();
    }
    if (threadIdx.x == 0) g_rowptr[NN] = carry;   // == EE
}

__global__ void csr_fill(const void* __restrict__ ei) {
    int e = blockIdx.x * blockDim.x + threadIdx.x;
    if (e >= EE) return;
    int d = load_idx(ei, 1, e);
    int pos = atomicAdd(&g_cursor[d], 1);
    g_eidx[g_rowptr[d] + pos] = load_idx(ei, 0, e);
}

// ---------------- SGEMM: C[M,NC] = A[M,128] @ B[128,NC] (+bias) -------------
// BM=64, BN=64, BK=32, 256 threads, 4x4 register tile per thread.
// A_FROM_H: 0 -> A = Aparam (harness input), 1 -> A = g_h
// C_SEL:    0 -> C = g_y, 1 -> C = g_z
template <int NC, int A_FROM_H, int C_SEL>
__global__ void __launch_bounds__(256) sgemm(const float* __restrict__ Aparam,
                                             const float* __restrict__ B,
                                             const float* __restrict__ bias,
                                             int M) {
    const float* A = A_FROM_H ? g_h : Aparam;
    float* C = C_SEL ? g_z : g_y;

    const int K = 128;
    __shared__ float As[32][65];   // k-major, padded
    __shared__ float Bs[32][64];   // k-major, natural

    int tid = threadIdx.x;
    int row0 = blockIdx.y * 64;
    int col0 = blockIdx.x * 64;
    int ty = tid >> 4;
    int tx = tid & 15;

    float acc[4][4] = {};

    for (int k0 = 0; k0 < K; k0 += 32) {
#pragma unroll
        for (int i = 0; i < 2; i++) {
            int f = tid + i * 256;
            int ar = f >> 3, ac = f & 7;
            float4 v = make_float4(0.f, 0.f, 0.f, 0.f);
            if (row0 + ar < M)
                v = *(const float4*)(A + (size_t)(row0 + ar) * K + k0 + ac * 4);
            As[ac * 4 + 0][ar] = v.x;
            As[ac * 4 + 1][ar] = v.y;
            As[ac * 4 + 2][ar] = v.z;
            As[ac * 4 + 3][ar] = v.w;
            int br = f >> 4, bc = f & 15;
            float4 w = *(const float4*)(B + (size_t)(k0 + br) * NC + col0 + bc * 4);
            *(float4*)&Bs[br][bc * 4] = w;
        }
        __syncthreads();

#pragma unroll
        for (int k = 0; k < 32; k++) {
            float a0 = As[k][ty * 4 + 0];
            float a1 = As[k][ty * 4 + 1];
            float a2 = As[k][ty * 4 + 2];
            float a3 = As[k][ty * 4 + 3];
            float4 b4 = *(float4*)&Bs[k][tx * 4];
            acc[0][0] += a0 * b4.x; acc[0][1] += a0 * b4.y; acc[0][2] += a0 * b4.z; acc[0][3] += a0 * b4.w;
            acc[1][0] += a1 * b4.x; acc[1][1] += a1 * b4.y; acc[1][2] += a1 * b4.z; acc[1][3] += a1 * b4.w;
            acc[2][0] += a2 * b4.x; acc[2][1] += a2 * b4.y; acc[2][2] += a2 * b4.z; acc[2][3] += a2 * b4.w;
            acc[3][0] += a3 * b4.x; acc[3][1] += a3 * b4.y; acc[3][2] += a3 * b4.z; acc[3][3] += a3 * b4.w;
        }
        __syncthreads();
    }

    float4 bb = make_float4(0.f, 0.f, 0.f, 0.f);
    if (bias) bb = *(const float4*)(bias + col0 + tx * 4);

#pragma unroll
    for (int i = 0; i < 4; i++) {
        int r = row0 + ty * 4 + i;
        if (r < M) {
            float4 o = make_float4(acc[i][0] + bb.x, acc[i][1] + bb.y,
                                   acc[i][2] + bb.z, acc[i][3] + bb.w);
            *(float4*)(C + (size_t)r * NC + col0 + tx * 4) = o;
        }
    }
}

// ---------------- fused gather + combine: warp per destination node ---------
// out[d] = act( mean_{s in N(d)} y[s]  +  z[d] )
// TO_H: 1 -> write g_h, 0 -> write outparam (harness d_out)
template <bool RELU, bool TO_H>
__global__ void __launch_bounds__(256) gather128(float* __restrict__ outparam) {
    int w = (blockIdx.x * blockDim.x + threadIdx.x) >> 5;
    if (w >= NN) return;
    int lane = threadIdx.x & 31;
    int beg = g_rowptr[w], end = g_rowptr[w + 1];

    float4 acc = make_float4(0.f, 0.f, 0.f, 0.f);
    int j = beg;
    for (; j + 2 <= end; j += 2) {
        int s0 = g_eidx[j];          // lane-uniform -> broadcast
        int s1 = g_eidx[j + 1];
        float4 a = *(const float4*)(g_y + (size_t)s0 * 128 + lane * 4);
        float4 b = *(const float4*)(g_y + (size_t)s1 * 128 + lane * 4);
        acc.x += a.x + b.x; acc.y += a.y + b.y;
        acc.z += a.z + b.z; acc.w += a.w + b.w;
    }
    if (j < end) {
        int s0 = g_eidx[j];
        float4 a = *(const float4*)(g_y + (size_t)s0 * 128 + lane * 4);
        acc.x += a.x; acc.y += a.y; acc.z += a.z; acc.w += a.w;
    }

    float dv = 1.0f / fmaxf((float)(end - beg), 1.0f);
    float4 zz = *(const float4*)(g_z + (size_t)w * 128 + lane * 4);
    float4 o;
    o.x = acc.x * dv + zz.x;
    o.y = acc.y * dv + zz.y;
    o.z = acc.z * dv + zz.z;
    o.w = acc.w * dv + zz.w;
    if (RELU) {
        o.x = fmaxf(o.x, 0.f); o.y = fmaxf(o.y, 0.f);
        o.z = fmaxf(o.z, 0.f); o.w = fmaxf(o.w, 0.f);
    }
    float* out = TO_H ? g_h : outparam;
    *(float4*)(out + (size_t)w * 128 + lane * 4) = o;
}

template <bool RELU, bool TO_H>
__global__ void __launch_bounds__(256) gather64(float* __restrict__ outparam) {
    int w = (blockIdx.x * blockDim.x + threadIdx.x) >> 5;
    if (w >= NN) return;
    int lane = threadIdx.x & 31;
    int beg = g_rowptr[w], end = g_rowptr[w + 1];

    float2 acc = make_float2(0.f, 0.f);
    int j = beg;
    for (; j + 2 <= end; j += 2) {
        int s0 = g_eidx[j];
        int s1 = g_eidx[j + 1];
        float2 a = *(const float2*)(g_y + (size_t)s0 * 64 + lane * 2);
        float2 b = *(const float2*)(g_y + (size_t)s1 * 64 + lane * 2);
        acc.x += a.x + b.x; acc.y += a.y + b.y;
    }
    if (j < end) {
        int s0 = g_eidx[j];
        float2 a = *(const float2*)(g_y + (size_t)s0 * 64 + lane * 2);
        acc.x += a.x; acc.y += a.y;
    }

    float dv = 1.0f / fmaxf((float)(end - beg), 1.0f);
    float2 zz = *(const float2*)(g_z + (size_t)w * 64 + lane * 2);
    float2 o;
    o.x = acc.x * dv + zz.x;
    o.y = acc.y * dv + zz.y;
    if (RELU) { o.x = fmaxf(o.x, 0.f); o.y = fmaxf(o.y, 0.f); }
    float* out = TO_H ? g_h : outparam;
    *(float2*)(out + (size_t)w * 64 + lane * 2) = o;
}

// ---------------- launch ----------------
extern "C" void kernel_launch(void* const* d_in, const int* in_sizes, int n_in,
                              void* d_out, int out_size) {
    const float* x = (const float*)d_in[0];
    const void* ei = d_in[1];
    const float* Wl0 = (const float*)d_in[2];
    const float* b0  = (const float*)d_in[3];
    const float* Wr0 = (const float*)d_in[4];
    const float* Wl1 = (const float*)d_in[5];
    const float* b1  = (const float*)d_in[6];
    const float* Wr1 = (const float*)d_in[7];
    const float* Wl2 = (const float*)d_in[8];
    const float* b2  = (const float*)d_in[9];
    const float* Wr2 = (const float*)d_in[10];
    float* out = (float*)d_out;

    // ---- CSR build (every call: graph-replay safe) ----
    detect_dtype<<<1, 32>>>(ei);
    csr_clear<<<(NN + 255) / 256, 256>>>();
    csr_hist<<<(EE + 255) / 256, 256>>>(ei);
    csr_scan<<<1, 1024>>>();
    csr_fill<<<(EE + 255) / 256, 256>>>(ei);

    dim3 g128(2, (NN + 63) / 64);
    dim3 g64(1, (NN + 63) / 64);
    const int gather_blocks = (NN * 32 + 255) / 256;

    // ---- layer 0: input = x ----
    sgemm<128, 0, 0><<<g128, 256>>>(x, Wl0, nullptr, NN);   // g_y = x @ Wl0
    sgemm<128, 0, 1><<<g128, 256>>>(x, Wr0, b0, NN);        // g_z = x @ Wr0 + b0
    gather128<true, true><<<gather_blocks, 256>>>(nullptr); // g_h

    // ---- layer 1: input = g_h ----
    sgemm<128, 1, 0><<<g128, 256>>>(nullptr, Wl1, nullptr, NN);
    sgemm<128, 1, 1><<<g128, 256>>>(nullptr, Wr1, b1, NN);
    gather128<true, true><<<gather_blocks, 256>>>(nullptr); // g_h

    // ---- layer 2: input = g_h, dout = 64 (multiply-first halves gather) ----
    sgemm<64, 1, 0><<<g64, 256>>>(nullptr, Wl2, nullptr, NN);
    sgemm<64, 1, 1><<<g64, 256>>>(nullptr, Wr2, b2, NN);
    gather64<false, false><<<gather_blocks, 256>>>(out);    // d_out
}

// round 10
// speedup vs baseline: 1.3819x; 1.3819x over previous
#include <cuda_runtime.h>
#include <cstdint>

#define NN 50000
#define EE 800000
#define SCAN_BLOCKS ((NN + 1023) / 1024)   // 49

// ---------------- scratch (device globals, referenced directly) -------------
__device__ float g_y[NN * 128];      // A @ Wl  (per layer)
__device__ float g_z[NN * 128];      // A @ Wr + b
__device__ float g_h[NN * 128];      // layer activation
__device__ int   g_rowptr[NN + 1];   // CSR row pointers (by dst)
__device__ int   g_cnt[NN];          // in-degree histogram
__device__ int   g_cursor[NN];       // fill cursors
__device__ int   g_eidx[EE];         // src node id per CSR slot
__device__ int   g_is64;             // edge_index dtype flag
__device__ int   g_bsum[SCAN_BLOCKS];
__device__ int   g_boff[SCAN_BLOCKS];

// ---------------- edge_index dtype detection --------------------------------
__global__ void detect_dtype(const void* __restrict__ ei) {
    if (threadIdx.x != 0 || blockIdx.x != 0) return;
    const long long* p = (const long long*)ei;
    int ok64 = 1;
    for (int i = 0; i < 64; i++) {
        long long v = p[i];
        if (v < 0 || v >= NN) { ok64 = 0; break; }
    }
    g_is64 = ok64;
}

// which: 0 = src row, 1 = dst row
__device__ __forceinline__ int load_idx(const void* __restrict__ ei, int which, int e) {
    if (g_is64) {
        const long long* p = (const long long*)ei;
        return (int)p[(size_t)which * EE + e];
    } else {
        const int* p = (const int*)ei;
        return p[(size_t)which * EE + e];
    }
}

// ---------------- CSR build ----------------
__global__ void csr_clear() {
    int i = blockIdx.x * blockDim.x + threadIdx.x;
    if (i < NN) { g_cnt[i] = 0; g_cursor[i] = 0; }
}

__global__ void csr_hist(const void* __restrict__ ei) {
    int e = blockIdx.x * blockDim.x + threadIdx.x;
    if (e < EE) atomicAdd(&g_cnt[load_idx(ei, 1, e)], 1);
}

// phase 1: per-block (1024-wide) exclusive scan via warp shuffles
__global__ void __launch_bounds__(1024) csr_scan1() {
    int i = blockIdx.x * 1024 + threadIdx.x;
    int v = (i < NN) ? g_cnt[i] : 0;
    int lane = threadIdx.x & 31, wid = threadIdx.x >> 5;
    int x = v;
#pragma unroll
    for (int off = 1; off < 32; off <<= 1) {
        int t = __shfl_up_sync(0xffffffffu, x, off);
        if (lane >= off) x += t;
    }
    __shared__ int wsum[32];
    if (lane == 31) wsum[wid] = x;
    __syncthreads();
    if (wid == 0) {
        int w = wsum[lane];
#pragma unroll
        for (int off = 1; off < 32; off <<= 1) {
            int t = __shfl_up_sync(0xffffffffu, w, off);
            if (lane >= off) w += t;
        }
        wsum[lane] = w;
    }
    __syncthreads();
    int base = wid ? wsum[wid - 1] : 0;
    if (i < NN) g_rowptr[i] = base + x - v;          // exclusive within block
    if (threadIdx.x == 0) g_bsum[blockIdx.x] = wsum[31];   // block total
}

// phase 2: serial scan of 49 block sums (trivial)
__global__ void csr_scan2() {
    if (threadIdx.x == 0 && blockIdx.x == 0) {
        int run = 0;
        for (int b = 0; b < SCAN_BLOCKS; b++) { g_boff[b] = run; run += g_bsum[b]; }
        g_rowptr[NN] = run;   // == EE
    }
}

// phase 3: add block offsets
__global__ void __launch_bounds__(1024) csr_scan3() {
    int i = blockIdx.x * 1024 + threadIdx.x;
    if (i < NN) g_rowptr[i] += g_boff[blockIdx.x];
}

__global__ void csr_fill(const void* __restrict__ ei) {
    int e = blockIdx.x * blockDim.x + threadIdx.x;
    if (e >= EE) return;
    int d = load_idx(ei, 1, e);
    int pos = atomicAdd(&g_cursor[d], 1);
    g_eidx[g_rowptr[d] + pos] = load_idx(ei, 0, e);
}

// ---------------- merged SGEMM pair: g_y = A@Bl, g_z = A@Br (+bias) ---------
// BM=64, BN=64(x2 outputs), BK=32, 256 threads, 2x 4x4 register tiles.
// A_FROM_H: 0 -> A = Aparam (harness input), 1 -> A = g_h
template <int NC, int A_FROM_H>
__global__ void __launch_bounds__(256) sgemm_pair(const float* __restrict__ Aparam,
                                                  const float* __restrict__ Bl,
                                                  const float* __restrict__ Br,
                                                  const float* __restrict__ bias,
                                                  int M) {
    const float* A = A_FROM_H ? g_h : Aparam;

    const int K = 128;
    __shared__ float As[32][65];    // k-major, padded
    __shared__ float Bsl[32][64];   // k-major
    __shared__ float Bsr[32][64];

    int tid = threadIdx.x;
    int row0 = blockIdx.y * 64;
    int col0 = blockIdx.x * 64;
    int ty = tid >> 4;
    int tx = tid & 15;

    float accl[4][4] = {};
    float accr[4][4] = {};

    for (int k0 = 0; k0 < K; k0 += 32) {
#pragma unroll
        for (int i = 0; i < 2; i++) {
            int f = tid + i * 256;          // 0..511
            // A tile: 64 rows x 8 float4 (K direction)
            int ar = f >> 3, ac = f & 7;
            float4 v = make_float4(0.f, 0.f, 0.f, 0.f);
            if (row0 + ar < M)
                v = *(const float4*)(A + (size_t)(row0 + ar) * K + k0 + ac * 4);
            As[ac * 4 + 0][ar] = v.x;
            As[ac * 4 + 1][ar] = v.y;
            As[ac * 4 + 2][ar] = v.z;
            As[ac * 4 + 3][ar] = v.w;
            // B tiles: 32 rows x 16 float4 each
            int br = f >> 4, bc = f & 15;
            float4 wl = *(const float4*)(Bl + (size_t)(k0 + br) * NC + col0 + bc * 4);
            float4 wr = *(const float4*)(Br + (size_t)(k0 + br) * NC + col0 + bc * 4);
            *(float4*)&Bsl[br][bc * 4] = wl;
            *(float4*)&Bsr[br][bc * 4] = wr;
        }
        __syncthreads();

#pragma unroll
        for (int k = 0; k < 32; k++) {
            float a0 = As[k][ty * 4 + 0];
            float a1 = As[k][ty * 4 + 1];
            float a2 = As[k][ty * 4 + 2];
            float a3 = As[k][ty * 4 + 3];
            float4 bl = *(float4*)&Bsl[k][tx * 4];
            float4 br = *(float4*)&Bsr[k][tx * 4];
            accl[0][0] += a0 * bl.x; accl[0][1] += a0 * bl.y; accl[0][2] += a0 * bl.z; accl[0][3] += a0 * bl.w;
            accl[1][0] += a1 * bl.x; accl[1][1] += a1 * bl.y; accl[1][2] += a1 * bl.z; accl[1][3] += a1 * bl.w;
            accl[2][0] += a2 * bl.x; accl[2][1] += a2 * bl.y; accl[2][2] += a2 * bl.z; accl[2][3] += a2 * bl.w;
            accl[3][0] += a3 * bl.x; accl[3][1] += a3 * bl.y; accl[3][2] += a3 * bl.z; accl[3][3] += a3 * bl.w;
            accr[0][0] += a0 * br.x; accr[0][1] += a0 * br.y; accr[0][2] += a0 * br.z; accr[0][3] += a0 * br.w;
            accr[1][0] += a1 * br.x; accr[1][1] += a1 * br.y; accr[1][2] += a1 * br.z; accr[1][3] += a1 * br.w;
            accr[2][0] += a2 * br.x; accr[2][1] += a2 * br.y; accr[2][2] += a2 * br.z; accr[2][3] += a2 * br.w;
            accr[3][0] += a3 * br.x; accr[3][1] += a3 * br.y; accr[3][2] += a3 * br.z; accr[3][3] += a3 * br.w;
        }
        __syncthreads();
    }

    float4 bb = *(const float4*)(bias + col0 + tx * 4);   // bias -> z side

#pragma unroll
    for (int i = 0; i < 4; i++) {
        int r = row0 + ty * 4 + i;
        if (r < M) {
            float4 oy = make_float4(accl[i][0], accl[i][1], accl[i][2], accl[i][3]);
            float4 oz = make_float4(accr[i][0] + bb.x, accr[i][1] + bb.y,
                                    accr[i][2] + bb.z, accr[i][3] + bb.w);
            *(float4*)(g_y + (size_t)r * NC + col0 + tx * 4) = oy;
            *(float4*)(g_z + (size_t)r * NC + col0 + tx * 4) = oz;
        }
    }
}

// ---------------- fused gather + combine: warp per destination node ---------
// out[d] = act( mean_{s in N(d)} y[s]  +  z[d] )
template <bool RELU, bool TO_H>
__global__ void __launch_bounds__(256) gather128(float* __restrict__ outparam) {
    int w = (blockIdx.x * blockDim.x + threadIdx.x) >> 5;
    if (w >= NN) return;
    int lane = threadIdx.x & 31;
    int beg = g_rowptr[w], end = g_rowptr[w + 1];

    float4 acc = make_float4(0.f, 0.f, 0.f, 0.f);
    int j = beg;
    for (; j + 2 <= end; j += 2) {
        int s0 = g_eidx[j];          // lane-uniform -> broadcast
        int s1 = g_eidx[j + 1];
        float4 a = *(const float4*)(g_y + (size_t)s0 * 128 + lane * 4);
        float4 b = *(const float4*)(g_y + (size_t)s1 * 128 + lane * 4);
        acc.x += a.x + b.x; acc.y += a.y + b.y;
        acc.z += a.z + b.z; acc.w += a.w + b.w;
    }
    if (j < end) {
        int s0 = g_eidx[j];
        float4 a = *(const float4*)(g_y + (size_t)s0 * 128 + lane * 4);
        acc.x += a.x; acc.y += a.y; acc.z += a.z; acc.w += a.w;
    }

    float dv = 1.0f / fmaxf((float)(end - beg), 1.0f);
    float4 zz = *(const float4*)(g_z + (size_t)w * 128 + lane * 4);
    float4 o;
    o.x = acc.x * dv + zz.x;
    o.y = acc.y * dv + zz.y;
    o.z = acc.z * dv + zz.z;
    o.w = acc.w * dv + zz.w;
    if (RELU) {
        o.x = fmaxf(o.x, 0.f); o.y = fmaxf(o.y, 0.f);
        o.z = fmaxf(o.z, 0.f); o.w = fmaxf(o.w, 0.f);
    }
    float* out = TO_H ? g_h : outparam;
    *(float4*)(out + (size_t)w * 128 + lane * 4) = o;
}

template <bool RELU, bool TO_H>
__global__ void __launch_bounds__(256) gather64(float* __restrict__ outparam) {
    int w = (blockIdx.x * blockDim.x + threadIdx.x) >> 5;
    if (w >= NN) return;
    int lane = threadIdx.x & 31;
    int beg = g_rowptr[w], end = g_rowptr[w + 1];

    float2 acc = make_float2(0.f, 0.f);
    int j = beg;
    for (; j + 2 <= end; j += 2) {
        int s0 = g_eidx[j];
        int s1 = g_eidx[j + 1];
        float2 a = *(const float2*)(g_y + (size_t)s0 * 64 + lane * 2);
        float2 b = *(const float2*)(g_y + (size_t)s1 * 64 + lane * 2);
        acc.x += a.x + b.x; acc.y += a.y + b.y;
    }
    if (j < end) {
        int s0 = g_eidx[j];
        float2 a = *(const float2*)(g_y + (size_t)s0 * 64 + lane * 2);
        acc.x += a.x; acc.y += a.y;
    }

    float dv = 1.0f / fmaxf((float)(end - beg), 1.0f);
    float2 zz = *(const float2*)(g_z + (size_t)w * 64 + lane * 2);
    float2 o;
    o.x = acc.x * dv + zz.x;
    o.y = acc.y * dv + zz.y;
    if (RELU) { o.x = fmaxf(o.x, 0.f); o.y = fmaxf(o.y, 0.f); }
    float* out = TO_H ? g_h : outparam;
    *(float2*)(out + (size_t)w * 64 + lane * 2) = o;
}

// ---------------- launch ----------------
extern "C" void kernel_launch(void* const* d_in, const int* in_sizes, int n_in,
                              void* d_out, int out_size) {
    const float* x = (const float*)d_in[0];
    const void* ei = d_in[1];
    const float* Wl0 = (const float*)d_in[2];
    const float* b0  = (const float*)d_in[3];
    const float* Wr0 = (const float*)d_in[4];
    const float* Wl1 = (const float*)d_in[5];
    const float* b1  = (const float*)d_in[6];
    const float* Wr1 = (const float*)d_in[7];
    const float* Wl2 = (const float*)d_in[8];
    const float* b2  = (const float*)d_in[9];
    const float* Wr2 = (const float*)d_in[10];
    float* out = (float*)d_out;

    // ---- CSR build (every call: graph-replay safe) ----
    detect_dtype<<<1, 32>>>(ei);
    csr_clear<<<(NN + 255) / 256, 256>>>();
    csr_hist<<<(EE + 255) / 256, 256>>>(ei);
    csr_scan1<<<SCAN_BLOCKS, 1024>>>();
    csr_scan2<<<1, 32>>>();
    csr_scan3<<<SCAN_BLOCKS, 1024>>>();
    csr_fill<<<(EE + 255) / 256, 256>>>(ei);

    dim3 g128(2, (NN + 63) / 64);
    dim3 g64(1, (NN + 63) / 64);
    const int gather_blocks = (NN * 32 + 255) / 256;

    // ---- layer 0: input = x ----
    sgemm_pair<128, 0><<<g128, 256>>>(x, Wl0, Wr0, b0, NN);
    gather128<true, true><<<gather_blocks, 256>>>(nullptr); // g_h

    // ---- layer 1: input = g_h ----
    sgemm_pair<128, 1><<<g128, 256>>>(nullptr, Wl1, Wr1, b1, NN);
    gather128<true, true><<<gather_blocks, 256>>>(nullptr); // g_h

    // ---- layer 2: input = g_h, dout = 64 (multiply-first halves gather) ----
    sgemm_pair<64, 1><<<g64, 256>>>(nullptr, Wl2, Wr2, b2, NN);
    gather64<false, false><<<gather_blocks, 256>>>(out);    // d_out
}

// round 11
// speedup vs baseline: 1.4949x; 1.0818x over previous
#include <cuda_runtime.h>
#include <cstdint>

#define NN 50000
#define EE 800000
#define SCAN_BLOCKS ((NN + 1023) / 1024)   // 49

// ---------------- scratch (device globals, referenced directly) -------------
__device__ float g_y[NN * 128];      // A @ Wl  (per layer)
__device__ float g_z[NN * 128];      // A @ Wr + b
__device__ float g_h[NN * 128];      // layer activation
__device__ int   g_rowptr[NN + 1];   // CSR row pointers (by dst)
__device__ int   g_cnt[NN];          // in-degree histogram
__device__ int   g_cursor[NN];       // fill cursors
__device__ int   g_eidx[EE];         // src node id per CSR slot
__device__ int   g_is64;             // edge_index dtype flag
__device__ int   g_bsum[SCAN_BLOCKS];
__device__ int   g_boff[SCAN_BLOCKS];

// ---------------- edge_index dtype detection --------------------------------
__global__ void detect_dtype(const void* __restrict__ ei) {
    if (threadIdx.x != 0 || blockIdx.x != 0) return;
    const long long* p = (const long long*)ei;
    int ok64 = 1;
    for (int i = 0; i < 64; i++) {
        long long v = p[i];
        if (v < 0 || v >= NN) { ok64 = 0; break; }
    }
    g_is64 = ok64;
}

__device__ __forceinline__ int load_idx(const void* __restrict__ ei, int which, int e) {
    if (g_is64) {
        const long long* p = (const long long*)ei;
        return (int)p[(size_t)which * EE + e];
    } else {
        const int* p = (const int*)ei;
        return p[(size_t)which * EE + e];
    }
}

// ---------------- CSR build ----------------
__global__ void csr_clear() {
    int i = blockIdx.x * blockDim.x + threadIdx.x;
    if (i < NN) { g_cnt[i] = 0; g_cursor[i] = 0; }
}

__global__ void csr_hist(const void* __restrict__ ei) {
    int e = blockIdx.x * blockDim.x + threadIdx.x;
    if (e < EE) atomicAdd(&g_cnt[load_idx(ei, 1, e)], 1);
}

__global__ void __launch_bounds__(1024) csr_scan1() {
    int i = blockIdx.x * 1024 + threadIdx.x;
    int v = (i < NN) ? g_cnt[i] : 0;
    int lane = threadIdx.x & 31, wid = threadIdx.x >> 5;
    int x = v;
#pragma unroll
    for (int off = 1; off < 32; off <<= 1) {
        int t = __shfl_up_sync(0xffffffffu, x, off);
        if (lane >= off) x += t;
    }
    __shared__ int wsum[32];
    if (lane == 31) wsum[wid] = x;
    __syncthreads();
    if (wid == 0) {
        int w = wsum[lane];
#pragma unroll
        for (int off = 1; off < 32; off <<= 1) {
            int t = __shfl_up_sync(0xffffffffu, w, off);
            if (lane >= off) w += t;
        }
        wsum[lane] = w;
    }
    __syncthreads();
    int base = wid ? wsum[wid - 1] : 0;
    if (i < NN) g_rowptr[i] = base + x - v;
    if (threadIdx.x == 0) g_bsum[blockIdx.x] = wsum[31];
}

__global__ void csr_scan2() {
    if (threadIdx.x == 0 && blockIdx.x == 0) {
        int run = 0;
        for (int b = 0; b < SCAN_BLOCKS; b++) { g_boff[b] = run; run += g_bsum[b]; }
        g_rowptr[NN] = run;
    }
}

__global__ void __launch_bounds__(1024) csr_scan3() {
    int i = blockIdx.x * 1024 + threadIdx.x;
    if (i < NN) g_rowptr[i] += g_boff[blockIdx.x];
}

__global__ void csr_fill(const void* __restrict__ ei) {
    int e = blockIdx.x * blockDim.x + threadIdx.x;
    if (e >= EE) return;
    int d = load_idx(ei, 1, e);
    int pos = atomicAdd(&g_cursor[d], 1);
    g_eidx[g_rowptr[d] + pos] = load_idx(ei, 0, e);
}

// ---------------- TF32 helpers ----------------
__device__ __forceinline__ uint32_t f2tf32(float x) {
    uint32_t r;
    asm("cvt.rna.tf32.f32 %0, %1;" : "=r"(r) : "f"(x));
    return r;
}
__device__ __forceinline__ void split_tf32(float v, uint32_t& hi, uint32_t& lo) {
    hi = f2tf32(v);
    lo = f2tf32(v - __uint_as_float(hi));
}
__device__ __forceinline__ void mma8(float* d, const uint32_t* a, const uint32_t* b) {
    asm volatile(
        "mma.sync.aligned.m16n8k8.row.col.f32.tf32.tf32.f32 "
        "{%0,%1,%2,%3}, {%4,%5,%6,%7}, {%8,%9}, {%0,%1,%2,%3};"
        : "+f"(d[0]), "+f"(d[1]), "+f"(d[2]), "+f"(d[3])
        : "r"(a[0]), "r"(a[1]), "r"(a[2]), "r"(a[3]), "r"(b[0]), "r"(b[1]));
}

// ---------------- merged TF32 GEMM pair: g_y = A@Bl, g_z = A@Br (+bias) -----
// BM=128, BN=64, BK=32, 256 threads = 8 warps (4 m x 2 n), warp tile 32x32 x2.
// 3xTF32: hi*hi + hi*lo + lo*hi per operand pair (near-fp32 accuracy).
template <int NC, int A_FROM_H>
__global__ void __launch_bounds__(256) sgemm_pair_tc(const float* __restrict__ Aparam,
                                                     const float* __restrict__ Bl,
                                                     const float* __restrict__ Br,
                                                     const float* __restrict__ bias,
                                                     int M) {
    const float* A = A_FROM_H ? g_h : Aparam;
    const int K = 128;

    __shared__ float As[32][132];    // k-major, stride 132 (frag loads CF)
    __shared__ float Bsl[32][68];    // k-major, stride 68  (frag loads CF)
    __shared__ float Bsr[32][68];

    int tid = threadIdx.x;
    int wid = tid >> 5;
    int lane = tid & 31;
    int warp_m = wid & 3;            // 0..3 -> 32-row slice
    int warp_n = wid >> 2;           // 0..1 -> 32-col slice
    int r = lane >> 2;               // groupID 0..7
    int c = lane & 3;                // threadID_in_group 0..3

    int row0 = blockIdx.y * 128;
    int col0 = blockIdx.x * 64;

    float accl[2][4][4] = {};        // [mtile][ntile][frag]
    float accr[2][4][4] = {};

    for (int k0 = 0; k0 < K; k0 += 32) {
        // ---- fill As (128x32, transposed to k-major) ----
#pragma unroll
        for (int i = 0; i < 4; i++) {
            int f = tid + i * 256;               // 0..1023 float4 ids
            int ar = f >> 3, ac = f & 7;
            float4 v = make_float4(0.f, 0.f, 0.f, 0.f);
            if (row0 + ar < M)
                v = *(const float4*)(A + (size_t)(row0 + ar) * K + k0 + ac * 4);
            As[ac * 4 + 0][ar] = v.x;
            As[ac * 4 + 1][ar] = v.y;
            As[ac * 4 + 2][ar] = v.z;
            As[ac * 4 + 3][ar] = v.w;
        }
        // ---- fill Bsl/Bsr (each 32x64, natural k-major) ----
#pragma unroll
        for (int i = 0; i < 2; i++) {
            int f = tid + i * 256;               // 0..511
            int br = f >> 4, bc = f & 15;
            float4 wl = *(const float4*)(Bl + (size_t)(k0 + br) * NC + col0 + bc * 4);
            float4 wr = *(const float4*)(Br + (size_t)(k0 + br) * NC + col0 + bc * 4);
            *(float4*)&Bsl[br][bc * 4] = wl;
            *(float4*)&Bsr[br][bc * 4] = wr;
        }
        __syncthreads();

#pragma unroll
        for (int kk = 0; kk < 32; kk += 8) {
            // A fragments (2 m-tiles), split hi/lo
            uint32_t ahi[2][4], alo[2][4];
#pragma unroll
            for (int mt = 0; mt < 2; mt++) {
                int m0 = warp_m * 32 + mt * 16;
                float a0 = As[kk + c][m0 + r];
                float a1 = As[kk + c][m0 + r + 8];
                float a2 = As[kk + c + 4][m0 + r];
                float a3 = As[kk + c + 4][m0 + r + 8];
                split_tf32(a0, ahi[mt][0], alo[mt][0]);
                split_tf32(a1, ahi[mt][1], alo[mt][1]);
                split_tf32(a2, ahi[mt][2], alo[mt][2]);
                split_tf32(a3, ahi[mt][3], alo[mt][3]);
            }
            // B fragments (4 n-tiles per matrix), split hi/lo
            uint32_t bhl[4][2], bll[4][2], bhr[4][2], blr[4][2];
#pragma unroll
            for (int nt = 0; nt < 4; nt++) {
                int n0 = warp_n * 32 + nt * 8 + r;
                float l0 = Bsl[kk + c][n0];
                float l1 = Bsl[kk + c + 4][n0];
                float r0 = Bsr[kk + c][n0];
                float r1 = Bsr[kk + c + 4][n0];
                split_tf32(l0, bhl[nt][0], bll[nt][0]);
                split_tf32(l1, bhl[nt][1], bll[nt][1]);
                split_tf32(r0, bhr[nt][0], blr[nt][0]);
                split_tf32(r1, bhr[nt][1], blr[nt][1]);
            }
            // 3xTF32 MMAs
#pragma unroll
            for (int mt = 0; mt < 2; mt++) {
#pragma unroll
                for (int nt = 0; nt < 4; nt++) {
                    mma8(accl[mt][nt], ahi[mt], bhl[nt]);
                    mma8(accl[mt][nt], ahi[mt], bll[nt]);
                    mma8(accl[mt][nt], alo[mt], bhl[nt]);
                    mma8(accr[mt][nt], ahi[mt], bhr[nt]);
                    mma8(accr[mt][nt], ahi[mt], blr[nt]);
                    mma8(accr[mt][nt], alo[mt], bhr[nt]);
                }
            }
        }
        __syncthreads();
    }

    // ---- epilogue ----
#pragma unroll
    for (int mt = 0; mt < 2; mt++) {
#pragma unroll
        for (int nt = 0; nt < 4; nt++) {
            int row = row0 + warp_m * 32 + mt * 16 + r;
            int col = col0 + warp_n * 32 + nt * 8 + 2 * c;
            float2 bb = *(const float2*)(bias + col);
            if (row < M) {
                *(float2*)(g_y + (size_t)row * NC + col) =
                    make_float2(accl[mt][nt][0], accl[mt][nt][1]);
                *(float2*)(g_z + (size_t)row * NC + col) =
                    make_float2(accr[mt][nt][0] + bb.x, accr[mt][nt][1] + bb.y);
            }
            if (row + 8 < M) {
                *(float2*)(g_y + (size_t)(row + 8) * NC + col) =
                    make_float2(accl[mt][nt][2], accl[mt][nt][3]);
                *(float2*)(g_z + (size_t)(row + 8) * NC + col) =
                    make_float2(accr[mt][nt][2] + bb.x, accr[mt][nt][3] + bb.y);
            }
        }
    }
}

// ---------------- fused gather + combine: warp per destination node ---------
template <bool RELU, bool TO_H>
__global__ void __launch_bounds__(256) gather128(float* __restrict__ outparam) {
    int w = (blockIdx.x * blockDim.x + threadIdx.x) >> 5;
    if (w >= NN) return;
    int lane = threadIdx.x & 31;
    int beg = g_rowptr[w], end = g_rowptr[w + 1];

    float4 acc = make_float4(0.f, 0.f, 0.f, 0.f);
    int j = beg;
    for (; j + 2 <= end; j += 2) {
        int s0 = g_eidx[j];
        int s1 = g_eidx[j + 1];
        float4 a = *(const float4*)(g_y + (size_t)s0 * 128 + lane * 4);
        float4 b = *(const float4*)(g_y + (size_t)s1 * 128 + lane * 4);
        acc.x += a.x + b.x; acc.y += a.y + b.y;
        acc.z += a.z + b.z; acc.w += a.w + b.w;
    }
    if (j < end) {
        int s0 = g_eidx[j];
        float4 a = *(const float4*)(g_y + (size_t)s0 * 128 + lane * 4);
        acc.x += a.x; acc.y += a.y; acc.z += a.z; acc.w += a.w;
    }

    float dv = 1.0f / fmaxf((float)(end - beg), 1.0f);
    float4 zz = *(const float4*)(g_z + (size_t)w * 128 + lane * 4);
    float4 o;
    o.x = acc.x * dv + zz.x;
    o.y = acc.y * dv + zz.y;
    o.z = acc.z * dv + zz.z;
    o.w = acc.w * dv + zz.w;
    if (RELU) {
        o.x = fmaxf(o.x, 0.f); o.y = fmaxf(o.y, 0.f);
        o.z = fmaxf(o.z, 0.f); o.w = fmaxf(o.w, 0.f);
    }
    float* out = TO_H ? g_h : outparam;
    *(float4*)(out + (size_t)w * 128 + lane * 4) = o;
}

template <bool RELU, bool TO_H>
__global__ void __launch_bounds__(256) gather64(float* __restrict__ outparam) {
    int w = (blockIdx.x * blockDim.x + threadIdx.x) >> 5;
    if (w >= NN) return;
    int lane = threadIdx.x & 31;
    int beg = g_rowptr[w], end = g_rowptr[w + 1];

    float2 acc = make_float2(0.f, 0.f);
    int j = beg;
    for (; j + 2 <= end; j += 2) {
        int s0 = g_eidx[j];
        int s1 = g_eidx[j + 1];
        float2 a = *(const float2*)(g_y + (size_t)s0 * 64 + lane * 2);
        float2 b = *(const float2*)(g_y + (size_t)s1 * 64 + lane * 2);
        acc.x += a.x + b.x; acc.y += a.y + b.y;
    }
    if (j < end) {
        int s0 = g_eidx[j];
        float2 a = *(const float2*)(g_y + (size_t)s0 * 64 + lane * 2);
        acc.x += a.x; acc.y += a.y;
    }

    float dv = 1.0f / fmaxf((float)(end - beg), 1.0f);
    float2 zz = *(const float2*)(g_z + (size_t)w * 64 + lane * 2);
    float2 o;
    o.x = acc.x * dv + zz.x;
    o.y = acc.y * dv + zz.y;
    if (RELU) { o.x = fmaxf(o.x, 0.f); o.y = fmaxf(o.y, 0.f); }
    float* out = TO_H ? g_h : outparam;
    *(float2*)(out + (size_t)w * 64 + lane * 2) = o;
}

// ---------------- launch ----------------
extern "C" void kernel_launch(void* const* d_in, const int* in_sizes, int n_in,
                              void* d_out, int out_size) {
    const float* x = (const float*)d_in[0];
    const void* ei = d_in[1];
    const float* Wl0 = (const float*)d_in[2];
    const float* b0  = (const float*)d_in[3];
    const float* Wr0 = (const float*)d_in[4];
    const float* Wl1 = (const float*)d_in[5];
    const float* b1  = (const float*)d_in[6];
    const float* Wr1 = (const float*)d_in[7];
    const float* Wl2 = (const float*)d_in[8];
    const float* b2  = (const float*)d_in[9];
    const float* Wr2 = (const float*)d_in[10];
    float* out = (float*)d_out;

    // ---- CSR build ----
    detect_dtype<<<1, 32>>>(ei);
    csr_clear<<<(NN + 255) / 256, 256>>>();
    csr_hist<<<(EE + 255) / 256, 256>>>(ei);
    csr_scan1<<<SCAN_BLOCKS, 1024>>>();
    csr_scan2<<<1, 32>>>();
    csr_scan3<<<SCAN_BLOCKS, 1024>>>();
    csr_fill<<<(EE + 255) / 256, 256>>>(ei);

    dim3 g128(2, (NN + 127) / 128);
    dim3 g64(1, (NN + 127) / 128);
    const int gather_blocks = (NN * 32 + 255) / 256;

    // ---- layer 0: input = x ----
    sgemm_pair_tc<128, 0><<<g128, 256>>>(x, Wl0, Wr0, b0, NN);
    gather128<true, true><<<gather_blocks, 256>>>(nullptr);

    // ---- layer 1: input = g_h ----
    sgemm_pair_tc<128, 1><<<g128, 256>>>(nullptr, Wl1, Wr1, b1, NN);
    gather128<true, true><<<gather_blocks, 256>>>(nullptr);

    // ---- layer 2: input = g_h, dout = 64 ----
    sgemm_pair_tc<64, 1><<<g64, 256>>>(nullptr, Wl2, Wr2, b2, NN);
    gather64<false, false><<<gather_blocks, 256>>>(out);
}